// round 12
// baseline (speedup 1.0000x reference)
#include <cuda_runtime.h>
#include <cuda_fp16.h>
#include <stdint.h>

// out[B,N] = x[B,K] @ W[K,N];  B=65536, K=512, N=64, fp32.
// fp16 HMMA, m-coarsened + split-K: warps 0-7 rows rg*32..+31 x K[0:256],
// warps 8-15 same rows x K[256:512]; smem partial-sum reduction at end.
// x: per-warp private cp.async pipeline, 5 stages x k16 (2KB fp32, swizzled).
// W: fp16 swizzled smem (64KB) converted in-prologue, ldsm per k16.
// FIX vs R10: CP_COMMIT every mainloop iteration (uniform group cadence) so
// cp.async.wait_group(N-1) guarantees the consumed stage is complete.

#define BATCH   65536
#define KDIM    512
#define NDIM    64
#define BM      256
#define THREADS 512
#define NK16    16            // k16 steps per warp (K-half = 256)
#define NSTAGE  5

#define SM_W    0             // 64KB fp16 swizzled W
#define SM_X    65536         // warp w: + w*(NSTAGE*2048); reused as reduction scratch
#define SMEM_TOTAL (65536 + 16 * NSTAGE * 2048)   // 229376

__device__ __forceinline__ void mma_f16(float* d, const uint32_t* a, const uint32_t* b) {
    asm volatile(
        "mma.sync.aligned.m16n8k16.row.col.f32.f16.f16.f32 "
        "{%0,%1,%2,%3}, {%4,%5,%6,%7}, {%8,%9}, {%0,%1,%2,%3};\n"
        : "+f"(d[0]), "+f"(d[1]), "+f"(d[2]), "+f"(d[3])
        : "r"(a[0]), "r"(a[1]), "r"(a[2]), "r"(a[3]), "r"(b[0]), "r"(b[1]));
}

__device__ __forceinline__ void ldsm_x4(uint32_t* r, uint32_t saddr) {
    asm volatile("ldmatrix.sync.aligned.m8n8.x4.shared.b16 {%0,%1,%2,%3}, [%4];"
        : "=r"(r[0]), "=r"(r[1]), "=r"(r[2]), "=r"(r[3]) : "r"(saddr));
}

__device__ __forceinline__ void cpasync16(uint32_t saddr, const void* gptr) {
    asm volatile("cp.async.cg.shared.global [%0], [%1], 16;\n"
        :: "r"(saddr), "l"(gptr));
}
#define CP_COMMIT()  asm volatile("cp.async.commit_group;\n" ::: "memory")
#define CP_WAIT(N)   asm volatile("cp.async.wait_group %0;\n" :: "n"(N) : "memory")

__device__ __forceinline__ uint32_t cvt2(float2 v) {
    __half2 h = __floats2half2_rn(v.x, v.y);
    return *reinterpret_cast<uint32_t*>(&h);
}

__device__ __forceinline__ float2 lds64(uint32_t saddr) {
    float2 v;
    asm volatile("ld.shared.v2.f32 {%0,%1}, [%2];"
        : "=f"(v.x), "=f"(v.y) : "r"(saddr));
    return v;
}

__device__ __forceinline__ void sts64(uint32_t saddr, float a, float b) {
    asm volatile("st.shared.v2.f32 [%0], {%1,%2};"
        :: "r"(saddr), "f"(a), "f"(b) : "memory");
}

__global__ __launch_bounds__(THREADS, 1)
void NN_57844619543085_kernel(const float* __restrict__ x,
                              const float* __restrict__ W,
                              float* __restrict__ out) {
    extern __shared__ __align__(1024) unsigned char sm[];
    const uint32_t smb = (uint32_t)__cvta_generic_to_shared(sm);

    const int t    = threadIdx.x;
    const int lane = t & 31;
    const int warp = t >> 5;
    const int rg   = warp & 7;    // row group: 32 rows
    const int kh   = warp >> 3;   // K half: 0 or 1
    const int block_row = blockIdx.x * BM;
    const int rowbase = block_row + rg * 32;
    const int koff  = kh * 256;

    // ---- fill addressing: stage = 32 rows x 16 k fp32 (2KB) ----
    const int row0 = lane >> 2;                 // 0..7
    const int g    = lane & 3;                  // 16B granule in 64B row-slice
    const uint32_t sxor = (uint32_t)(((lane >> 3) & 1) << 5);
    const uint32_t fill_off = (uint32_t)row0 * 64 + ((uint32_t)(g * 16) ^ sxor);
    const float* xsrc = x + (size_t)(rowbase + row0) * KDIM + koff + g * 4;
    const uint32_t xw = smb + SM_X + warp * (NSTAGE * 2048);

#define FILL(slot, j)                                                          \
    {                                                                          \
        uint32_t d_ = xw + (slot) * 2048 + fill_off;                           \
        const float* s_ = xsrc + (j) * 16;                                     \
        cpasync16(d_,        s_);                                              \
        cpasync16(d_ + 512,  s_ + 8 * KDIM);                                   \
        cpasync16(d_ + 1024, s_ + 16 * KDIM);                                  \
        cpasync16(d_ + 1536, s_ + 24 * KDIM);                                  \
    }

    // ---- prologue: stages 0..4 in flight first ----
    FILL(0, 0); CP_COMMIT();
    FILL(1, 1); CP_COMMIT();
    FILL(2, 2); CP_COMMIT();
    FILL(3, 3); CP_COMMIT();
    FILL(4, 4); CP_COMMIT();

    // ---- W conversion: fp32 gmem -> fp16 swizzled smem (overlaps fills) ----
    {
        const int wn_ = t & 63;
        const int wq_ = t >> 6;                  // 0..7, 64 k each
        const uint32_t wrow = smb + SM_W + wn_ * 128;
        const int nsw = (wn_ & 7) << 4;
#pragma unroll 4
        for (int i = 0; i < 16; ++i) {
            int k = wq_ * 64 + i * 4;
            float f0 = __ldg(&W[(k + 0) * NDIM + wn_]);
            float f1 = __ldg(&W[(k + 1) * NDIM + wn_]);
            float f2 = __ldg(&W[(k + 2) * NDIM + wn_]);
            float f3 = __ldg(&W[(k + 3) * NDIM + wn_]);
            uint32_t p0 = cvt2(make_float2(f0, f1));
            uint32_t p1 = cvt2(make_float2(f2, f3));
            uint32_t off = (uint32_t)((k >> 6) * 8192)
                         + (uint32_t)(((k & 63) * 2) ^ nsw);
            asm volatile("st.shared.v2.b32 [%0], {%1,%2};"
                :: "r"(wrow + off), "r"(p0), "r"(p1) : "memory");
        }
    }

    // ---- consume addressing ----
    const uint32_t o_lo = ((uint32_t)((lane & 3) * 8))      ^ sxor;
    const uint32_t o_hi = ((uint32_t)((lane & 3) * 8 + 32)) ^ sxor;
    const uint32_t rb[4] = { (uint32_t)row0 * 64,
                             (uint32_t)(row0 + 8) * 64,
                             (uint32_t)(row0 + 16) * 64,
                             (uint32_t)(row0 + 24) * 64 };
    const int sub  = lane >> 3;
    const int lrow = lane & 7;
    const int kbase16 = kh * 16;

    float acc[2][8][4];
#pragma unroll
    for (int mt = 0; mt < 2; ++mt)
#pragma unroll
        for (int nt = 0; nt < 8; ++nt)
#pragma unroll
            for (int q = 0; q < 4; ++q) acc[mt][nt][q] = 0.0f;

    __syncthreads();   // W tile visible CTA-wide

    int slot = 0;
#pragma unroll 1
    for (int j = 0; j < NK16; ++j) {
        CP_WAIT(NSTAGE - 1);
        __syncwarp();

        const uint32_t xb = xw + slot * 2048;

        // ---- A fragments: 2 m-tiles (rows +0/+16), fp32 LDS + cvt ----
        uint32_t a[2][4];
#pragma unroll
        for (int mt = 0; mt < 2; ++mt) {
            a[mt][0] = cvt2(lds64(xb + rb[2 * mt]     + o_lo));
            a[mt][1] = cvt2(lds64(xb + rb[2 * mt + 1] + o_lo));
            a[mt][2] = cvt2(lds64(xb + rb[2 * mt]     + o_hi));
            a[mt][3] = cvt2(lds64(xb + rb[2 * mt + 1] + o_hi));
        }

        // ---- refill this slot for j+NSTAGE; COMMIT EVERY ITERATION ----
        if (j + NSTAGE < NK16) FILL(slot, j + NSTAGE);
        CP_COMMIT();

        // ---- B fragments + 16 MMAs ----
        const int kk = kbase16 + j;
        const uint32_t wbase = smb + SM_W + (kk >> 2) * 8192;
        const int ksic = kk & 3;
        uint32_t b[8][2];
#pragma unroll
        for (int p = 0; p < 4; ++p) {
            int n = (2 * p + (sub >> 1)) * 8 + lrow;
            uint32_t boff = (uint32_t)n * 128
                          + ((ksic * 32 + (sub & 1) * 16) ^ (lrow << 4));
            uint32_t tmp[4];
            ldsm_x4(tmp, wbase + boff);
            b[2*p][0]   = tmp[0]; b[2*p][1]   = tmp[1];
            b[2*p+1][0] = tmp[2]; b[2*p+1][1] = tmp[3];
        }
#pragma unroll
        for (int mt = 0; mt < 2; ++mt)
#pragma unroll
            for (int nt = 0; nt < 8; ++nt)
                mma_f16(acc[mt][nt], a[mt], b[nt]);

        slot = (slot == NSTAGE - 1) ? 0 : slot + 1;
    }

    // ---- split-K reduction: warps 8-15 dump partials, warps 0-7 add+store ----
    __syncthreads();   // all warps done with x stages; reuse SM_X as scratch

    const uint32_t blk = smb + SM_X + rg * 8192;   // 32 rows x 64 cols fp32
    const uint32_t eoff = (uint32_t)(lane >> 2) * 256 + (uint32_t)((lane & 3) * 2) * 4;

    if (kh == 1) {
#pragma unroll
        for (int mt = 0; mt < 2; ++mt)
#pragma unroll
            for (int p = 0; p < 2; ++p)
#pragma unroll
                for (int nt = 0; nt < 8; ++nt) {
                    uint32_t addr = blk + eoff + (uint32_t)(mt * 16 + p * 8) * 256
                                  + (uint32_t)(nt * 8) * 4;
                    sts64(addr, acc[mt][nt][p * 2], acc[mt][nt][p * 2 + 1]);
                }
    }
    __syncthreads();
    if (kh == 0) {
#pragma unroll
        for (int mt = 0; mt < 2; ++mt)
#pragma unroll
            for (int p = 0; p < 2; ++p) {
                int grow = rowbase + mt * 16 + p * 8 + (lane >> 2);
#pragma unroll
                for (int nt = 0; nt < 8; ++nt) {
                    uint32_t addr = blk + eoff + (uint32_t)(mt * 16 + p * 8) * 256
                                  + (uint32_t)(nt * 8) * 4;
                    float2 v = lds64(addr);
                    int gcol = nt * 8 + (lane & 3) * 2;
                    __stcs((float2*)(out + (size_t)grow * NDIM + gcol),
                           make_float2(acc[mt][nt][p * 2] + v.x,
                                       acc[mt][nt][p * 2 + 1] + v.y));
                }
            }
    }
}

extern "C" void kernel_launch(void* const* d_in, const int* in_sizes, int n_in,
                              void* d_out, int out_size) {
    const float* x = (const float*)d_in[0];   // [65536, 512]
    const float* W = (const float*)d_in[1];   // [512, 64]
    float* out = (float*)d_out;               // [65536, 64]

    cudaFuncSetAttribute(NN_57844619543085_kernel,
                         cudaFuncAttributeMaxDynamicSharedMemorySize, SMEM_TOTAL);

    NN_57844619543085_kernel<<<BATCH / BM, THREADS, SMEM_TOTAL>>>(x, W, out);
}

// round 13
// speedup vs baseline: 1.1996x; 1.1996x over previous
#include <cuda_runtime.h>
#include <cuda_fp16.h>
#include <stdint.h>

// out[B,N] = x[B,K] @ W[K,N];  B=65536, K=512, N=64, fp32.
// Persistent-CTA fp16 HMMA (norm rel_err ~3e-4 < 1e-3).
// grid = #SMs, 1 CTA/SM, 16 warps. Each warp independently processes 16-row
// tiles rt = warp*G + bid + i*16G (4096 tiles) -> per-SM byte load balanced,
// no wave-quantization tail. Per-warp private 5-deep cp.async x pipeline runs
// seamlessly across tile boundaries. W fp16 swizzled smem (64KB) once.

#define BATCH   65536
#define KDIM    512
#define NDIM    64
#define NTILES  (BATCH / 16)   // 4096
#define THREADS 512
#define NSTAGE  5

#define SM_W    0              // 64KB fp16 swizzled W
#define SM_X    65536          // warp w slot s: + (w*NSTAGE+s)*2048
#define SMEM_TOTAL (65536 + 16 * NSTAGE * 2048)   // 229376

__device__ __forceinline__ void mma_f16(float* d, const uint32_t* a, const uint32_t* b) {
    asm volatile(
        "mma.sync.aligned.m16n8k16.row.col.f32.f16.f16.f32 "
        "{%0,%1,%2,%3}, {%4,%5,%6,%7}, {%8,%9}, {%0,%1,%2,%3};\n"
        : "+f"(d[0]), "+f"(d[1]), "+f"(d[2]), "+f"(d[3])
        : "r"(a[0]), "r"(a[1]), "r"(a[2]), "r"(a[3]), "r"(b[0]), "r"(b[1]));
}

__device__ __forceinline__ void ldsm_x4(uint32_t* r, uint32_t saddr) {
    asm volatile("ldmatrix.sync.aligned.m8n8.x4.shared.b16 {%0,%1,%2,%3}, [%4];"
        : "=r"(r[0]), "=r"(r[1]), "=r"(r[2]), "=r"(r[3]) : "r"(saddr));
}

__device__ __forceinline__ void cpasync16(uint32_t saddr, const void* gptr) {
    asm volatile("cp.async.cg.shared.global [%0], [%1], 16;\n"
        :: "r"(saddr), "l"(gptr));
}
#define CP_COMMIT()  asm volatile("cp.async.commit_group;\n" ::: "memory")
#define CP_WAIT(N)   asm volatile("cp.async.wait_group %0;\n" :: "n"(N) : "memory")

__device__ __forceinline__ uint32_t cvt2(float2 v) {
    __half2 h = __floats2half2_rn(v.x, v.y);
    return *reinterpret_cast<uint32_t*>(&h);
}

__device__ __forceinline__ float2 lds64(uint32_t saddr) {
    float2 v;
    asm volatile("ld.shared.v2.f32 {%0,%1}, [%2];"
        : "=f"(v.x), "=f"(v.y) : "r"(saddr));
    return v;
}

__global__ __launch_bounds__(THREADS, 1)
void NN_57844619543085_kernel(const float* __restrict__ x,
                              const float* __restrict__ W,
                              float* __restrict__ out) {
    extern __shared__ __align__(1024) unsigned char sm[];
    const uint32_t smb = (uint32_t)__cvta_generic_to_shared(sm);

    const int t    = threadIdx.x;
    const int lane = t & 31;
    const int warp = t >> 5;
    const int G    = gridDim.x;

    // ---- warp's tile sequence: rt0, rt0+16G, ... < NTILES ----
    const int rt0      = warp * G + blockIdx.x;
    const int rtstride = 16 * G;
    const int nt       = (NTILES - 1 - rt0) / rtstride + 1;   // rt0 < 2432 < NTILES always
    const int total    = nt * 16;          // half-chunk iterations (16 per tile)

    // ---- fill addressing within a stage (16 rows x 32 k fp32 = 2KB) ----
    const int rbase = lane >> 3;           // 0..3
    const int g     = lane & 7;            // 16B granule in 128B row
    const uint32_t fill_off = (uint32_t)rbase * 128
                            + (uint32_t)((g * 16) ^ (rbase << 5));
    const uint32_t xw = smb + SM_X + warp * (NSTAGE * 2048);

    // fill-side state
    const float* fsrc = x + ((size_t)rt0 * 16 + rbase) * KDIM + g * 4;
    int h_f = 0, sf = 0, ff = 0;
    const size_t tile_jump = (size_t)rtstride * 16 * KDIM;

#define ADV()                                                                  \
    {                                                                          \
        if (ff < total) {                                                      \
            uint32_t d_ = xw + sf * 2048 + fill_off;                           \
            const float* s_ = fsrc + h_f * 32;                                 \
            cpasync16(d_,        s_);                                          \
            cpasync16(d_ + 512,  s_ + 4 * KDIM);                               \
            cpasync16(d_ + 1024, s_ + 8 * KDIM);                               \
            cpasync16(d_ + 1536, s_ + 12 * KDIM);                              \
        }                                                                      \
        CP_COMMIT();                                                           \
        ++ff; sf = (sf == NSTAGE - 1) ? 0 : sf + 1;                            \
        if (++h_f == 16) { h_f = 0; fsrc += tile_jump; }                       \
    }

    // ---- prologue: 5 stages in flight ----
    ADV(); ADV(); ADV(); ADV(); ADV();

    // ---- W conversion: fp32 gmem -> fp16 swizzled smem (overlaps fills) ----
    {
        const int wn_ = t & 63;
        const int wq_ = t >> 6;              // 0..7, 64 k each
        const uint32_t wrow = smb + SM_W + wn_ * 128;
        const int nsw = (wn_ & 7) << 4;
#pragma unroll 4
        for (int i = 0; i < 16; ++i) {
            int k = wq_ * 64 + i * 4;
            float f0 = __ldg(&W[(k + 0) * NDIM + wn_]);
            float f1 = __ldg(&W[(k + 1) * NDIM + wn_]);
            float f2 = __ldg(&W[(k + 2) * NDIM + wn_]);
            float f3 = __ldg(&W[(k + 3) * NDIM + wn_]);
            uint32_t p0 = cvt2(make_float2(f0, f1));
            uint32_t p1 = cvt2(make_float2(f2, f3));
            uint32_t off = (uint32_t)((k >> 6) * 8192)
                         + (uint32_t)(((k & 63) * 2) ^ nsw);
            asm volatile("st.shared.v2.b32 [%0], {%1,%2};"
                :: "r"(wrow + off), "r"(p0), "r"(p1) : "memory");
        }
    }

    // ---- consume addressing ----
    const int r  = lane >> 2;               // 0..7
    const int c8 = (lane & 3) * 8;
    const uint32_t sxor = (uint32_t)((r & 3) << 5);
    const uint32_t o_lo[2] = { (uint32_t)(c8)      ^ sxor,
                               (uint32_t)(64 + c8) ^ sxor };
    const uint32_t o_hi[2] = { (uint32_t)(32 + c8) ^ sxor,
                               (uint32_t)(96 + c8) ^ sxor };
    const uint32_t rb0 = (uint32_t)r * 128;
    const uint32_t rb8 = rb0 + 1024;

    const int sub  = lane >> 3;
    const int lrow = lane & 7;

    float acc[8][4];
#pragma unroll
    for (int nt8 = 0; nt8 < 8; ++nt8)
#pragma unroll
        for (int q = 0; q < 4; ++q) acc[nt8][q] = 0.0f;

    __syncthreads();   // W tile visible CTA-wide

    int rt_c = rt0;
    int slot = 0;
#pragma unroll 1
    for (int f = 0; f < total; ++f) {
        CP_WAIT(NSTAGE - 1);
        __syncwarp();

        const uint32_t xb = xw + slot * 2048;
        const int h = f & 15;

        // ---- A fragments for both k16 of this half-chunk ----
        uint32_t a0[4], a1[4];
        a0[0] = cvt2(lds64(xb + rb0 + o_lo[0]));
        a0[1] = cvt2(lds64(xb + rb8 + o_lo[0]));
        a0[2] = cvt2(lds64(xb + rb0 + o_hi[0]));
        a0[3] = cvt2(lds64(xb + rb8 + o_hi[0]));
        a1[0] = cvt2(lds64(xb + rb0 + o_lo[1]));
        a1[1] = cvt2(lds64(xb + rb8 + o_lo[1]));
        a1[2] = cvt2(lds64(xb + rb0 + o_hi[1]));
        a1[3] = cvt2(lds64(xb + rb8 + o_hi[1]));

        // ---- advance the fill pipeline (uniform commit cadence) ----
        ADV();

        // ---- B ldsm + MMAs for both k16 steps ----
#pragma unroll
        for (int j = 0; j < 2; ++j) {
            const int kk = h * 2 + j;
            const uint32_t wbase = smb + SM_W + (kk >> 2) * 8192;
            const int ksic = kk & 3;
            const uint32_t* a = (j == 0) ? a0 : a1;
            uint32_t b[8][2];
#pragma unroll
            for (int p = 0; p < 4; ++p) {
                int n = (2 * p + (sub >> 1)) * 8 + lrow;
                uint32_t boff = (uint32_t)n * 128
                              + ((ksic * 32 + (sub & 1) * 16) ^ (lrow << 4));
                uint32_t tmp[4];
                ldsm_x4(tmp, wbase + boff);
                b[2*p][0]   = tmp[0]; b[2*p][1]   = tmp[1];
                b[2*p+1][0] = tmp[2]; b[2*p+1][1] = tmp[3];
            }
#pragma unroll
            for (int nt8 = 0; nt8 < 8; ++nt8)
                mma_f16(acc[nt8], a, b[nt8]);
        }

        // ---- tile boundary: store + reset ----
        if (h == 15) {
            const int arow = rt_c * 16 + (lane >> 2);
#pragma unroll
            for (int nt8 = 0; nt8 < 8; ++nt8) {
                int gcol = nt8 * 8 + (lane & 3) * 2;
                __stcs((float2*)(out + (size_t)arow * NDIM + gcol),
                       make_float2(acc[nt8][0], acc[nt8][1]));
                __stcs((float2*)(out + (size_t)(arow + 8) * NDIM + gcol),
                       make_float2(acc[nt8][2], acc[nt8][3]));
#pragma unroll
                for (int q = 0; q < 4; ++q) acc[nt8][q] = 0.0f;
            }
            rt_c += rtstride;
        }

        slot = (slot == NSTAGE - 1) ? 0 : slot + 1;
    }
}

extern "C" void kernel_launch(void* const* d_in, const int* in_sizes, int n_in,
                              void* d_out, int out_size) {
    const float* x = (const float*)d_in[0];   // [65536, 512]
    const float* W = (const float*)d_in[1];   // [512, 64]
    float* out = (float*)d_out;               // [65536, 64]

    cudaFuncSetAttribute(NN_57844619543085_kernel,
                         cudaFuncAttributeMaxDynamicSharedMemorySize, SMEM_TOTAL);

    int sms = 148;
    cudaDeviceGetAttribute(&sms, cudaDevAttrMultiProcessorCount, 0);

    NN_57844619543085_kernel<<<sms, THREADS, SMEM_TOTAL>>>(x, W, out);
}

// round 15
// speedup vs baseline: 1.2419x; 1.0353x over previous
#include <cuda_runtime.h>
#include <cuda_fp16.h>
#include <stdint.h>

// out[B,N] = x[B,K] @ W[K,N];  B=65536, K=512, N=64, fp32.
// Persistent-CTA fp16 HMMA (norm rel_err ~3e-4 < 1e-3).
// grid = #SMs, 1 CTA/SM, 16 warps; warp-flat 16-row tiles, per-warp private
// 5-deep cp.async x pipeline running seamlessly across tiles; W fp16 swizzled
// smem once. Mainloop unrolled x2 -> literal ksic, per-pair wbase/store check.

#define BATCH   65536
#define KDIM    512
#define NDIM    64
#define NTILES  (BATCH / 16)   // 4096
#define THREADS 512
#define NSTAGE  5

#define SM_W    0              // 64KB fp16 swizzled W
#define SM_X    65536          // warp w slot s: + (w*NSTAGE+s)*2048
#define SMEM_TOTAL (65536 + 16 * NSTAGE * 2048)   // 229376

__device__ __forceinline__ void mma_f16(float* d, const uint32_t* a, const uint32_t* b) {
    asm volatile(
        "mma.sync.aligned.m16n8k16.row.col.f32.f16.f16.f32 "
        "{%0,%1,%2,%3}, {%4,%5,%6,%7}, {%8,%9}, {%0,%1,%2,%3};\n"
        : "+f"(d[0]), "+f"(d[1]), "+f"(d[2]), "+f"(d[3])
        : "r"(a[0]), "r"(a[1]), "r"(a[2]), "r"(a[3]), "r"(b[0]), "r"(b[1]));
}

__device__ __forceinline__ void ldsm_x4(uint32_t* r, uint32_t saddr) {
    asm volatile("ldmatrix.sync.aligned.m8n8.x4.shared.b16 {%0,%1,%2,%3}, [%4];"
        : "=r"(r[0]), "=r"(r[1]), "=r"(r[2]), "=r"(r[3]) : "r"(saddr));
}

__device__ __forceinline__ void cpasync16(uint32_t saddr, const void* gptr) {
    asm volatile("cp.async.cg.shared.global [%0], [%1], 16;\n"
        :: "r"(saddr), "l"(gptr));
}
#define CP_COMMIT()  asm volatile("cp.async.commit_group;\n" ::: "memory")
#define CP_WAIT(N)   asm volatile("cp.async.wait_group %0;\n" :: "n"(N) : "memory")

__device__ __forceinline__ uint32_t cvt2(float2 v) {
    __half2 h = __floats2half2_rn(v.x, v.y);
    return *reinterpret_cast<uint32_t*>(&h);
}

__device__ __forceinline__ float2 lds64(uint32_t saddr) {
    float2 v;
    asm volatile("ld.shared.v2.f32 {%0,%1}, [%2];"
        : "=f"(v.x), "=f"(v.y) : "r"(saddr));
    return v;
}

__global__ __launch_bounds__(THREADS, 1)
void NN_57844619543085_kernel(const float* __restrict__ x,
                              const float* __restrict__ W,
                              float* __restrict__ out) {
    extern __shared__ __align__(1024) unsigned char sm[];
    const uint32_t smb = (uint32_t)__cvta_generic_to_shared(sm);

    const int t    = threadIdx.x;
    const int lane = t & 31;
    const int warp = t >> 5;
    const int G    = gridDim.x;

    // ---- warp's tile sequence: rt0, rt0+16G, ... < NTILES ----
    const int rt0      = warp * G + blockIdx.x;
    const int rtstride = 16 * G;
    const int nt       = (NTILES - 1 - rt0) / rtstride + 1;
    const int npairs   = nt * 8;           // unrolled-pair iterations (8 per tile)
    const int total    = nt * 16;          // fill half-chunks

    // ---- fill addressing within a stage (16 rows x 32 k fp32 = 2KB) ----
    const int rbase = lane >> 3;           // 0..3
    const int g     = lane & 7;            // 16B granule in 128B row
    const uint32_t fill_off = (uint32_t)rbase * 128
                            + (uint32_t)((g * 16) ^ (rbase << 5));
    const uint32_t xw = smb + SM_X + warp * (NSTAGE * 2048);

    // fill-side state
    const float* fsrc = x + ((size_t)rt0 * 16 + rbase) * KDIM + g * 4;
    int h_f = 0, sf = 0, ff = 0;
    const size_t tile_jump = (size_t)rtstride * 16 * KDIM;

#define ADV()                                                                  \
    {                                                                          \
        if (ff < total) {                                                      \
            uint32_t d_ = xw + sf * 2048 + fill_off;                           \
            const float* s_ = fsrc + h_f * 32;                                 \
            cpasync16(d_,        s_);                                          \
            cpasync16(d_ + 512,  s_ + 4 * KDIM);                               \
            cpasync16(d_ + 1024, s_ + 8 * KDIM);                               \
            cpasync16(d_ + 1536, s_ + 12 * KDIM);                              \
        }                                                                      \
        CP_COMMIT();                                                           \
        ++ff; sf = (sf == NSTAGE - 1) ? 0 : sf + 1;                            \
        if (++h_f == 16) { h_f = 0; fsrc += tile_jump; }                       \
    }

    // ---- prologue: 5 stages in flight ----
    ADV(); ADV(); ADV(); ADV(); ADV();

    // ---- W conversion: fp32 gmem -> fp16 swizzled smem (overlaps fills) ----
    {
        const int wn_ = t & 63;
        const int wq_ = t >> 6;              // 0..7, 64 k each
        const uint32_t wrow = smb + SM_W + wn_ * 128;
        const int nsw = (wn_ & 7) << 4;
#pragma unroll 4
        for (int i = 0; i < 16; ++i) {
            int k = wq_ * 64 + i * 4;
            float f0 = __ldg(&W[(k + 0) * NDIM + wn_]);
            float f1 = __ldg(&W[(k + 1) * NDIM + wn_]);
            float f2 = __ldg(&W[(k + 2) * NDIM + wn_]);
            float f3 = __ldg(&W[(k + 3) * NDIM + wn_]);
            uint32_t p0 = cvt2(make_float2(f0, f1));
            uint32_t p1 = cvt2(make_float2(f2, f3));
            uint32_t off = (uint32_t)((k >> 6) * 8192)
                         + (uint32_t)(((k & 63) * 2) ^ nsw);
            asm volatile("st.shared.v2.b32 [%0], {%1,%2};"
                :: "r"(wrow + off), "r"(p0), "r"(p1) : "memory");
        }
    }

    // ---- consume addressing ----
    const int r  = lane >> 2;               // 0..7
    const int c8 = (lane & 3) * 8;
    const uint32_t sxor = (uint32_t)((r & 3) << 5);
    const uint32_t o_lo[2] = { (uint32_t)(c8)      ^ sxor,
                               (uint32_t)(64 + c8) ^ sxor };
    const uint32_t o_hi[2] = { (uint32_t)(32 + c8) ^ sxor,
                               (uint32_t)(96 + c8) ^ sxor };
    const uint32_t rb0 = (uint32_t)r * 128;
    const uint32_t rb8 = rb0 + 1024;

    const int sub  = lane >> 3;
    const int lrow = lane & 7;

    float acc[8][4];
#pragma unroll
    for (int nt8 = 0; nt8 < 8; ++nt8)
#pragma unroll
        for (int q = 0; q < 4; ++q) acc[nt8][q] = 0.0f;

    __syncthreads();   // W tile visible CTA-wide

    // one consume half-chunk with LITERAL ksic pair (KS0, KS1)
#define HALF(WB, KS0, KS1)                                                     \
    {                                                                          \
        CP_WAIT(NSTAGE - 1);                                                   \
        __syncwarp();                                                          \
        const uint32_t xb = xw + slot * 2048;                                  \
        uint32_t a0[4], a1[4];                                                 \
        a0[0] = cvt2(lds64(xb + rb0 + o_lo[0]));                               \
        a0[1] = cvt2(lds64(xb + rb8 + o_lo[0]));                               \
        a0[2] = cvt2(lds64(xb + rb0 + o_hi[0]));                               \
        a0[3] = cvt2(lds64(xb + rb8 + o_hi[0]));                               \
        a1[0] = cvt2(lds64(xb + rb0 + o_lo[1]));                               \
        a1[1] = cvt2(lds64(xb + rb8 + o_lo[1]));                               \
        a1[2] = cvt2(lds64(xb + rb0 + o_hi[1]));                               \
        a1[3] = cvt2(lds64(xb + rb8 + o_hi[1]));                               \
        ADV();                                                                 \
        uint32_t b[8][2];                                                      \
        _Pragma("unroll")                                                      \
        for (int p = 0; p < 4; ++p) {                                          \
            int n = (2 * p + (sub >> 1)) * 8 + lrow;                           \
            uint32_t boff = (uint32_t)n * 128                                  \
                          + (((KS0) * 32 + (sub & 1) * 16) ^ (lrow << 4));     \
            uint32_t tmp[4];                                                   \
            ldsm_x4(tmp, (WB) + boff);                                         \
            b[2*p][0]   = tmp[0]; b[2*p][1]   = tmp[1];                        \
            b[2*p+1][0] = tmp[2]; b[2*p+1][1] = tmp[3];                        \
        }                                                                      \
        _Pragma("unroll")                                                      \
        for (int nt8 = 0; nt8 < 8; ++nt8) mma_f16(acc[nt8], a0, b[nt8]);       \
        _Pragma("unroll")                                                      \
        for (int p = 0; p < 4; ++p) {                                          \
            int n = (2 * p + (sub >> 1)) * 8 + lrow;                           \
            uint32_t boff = (uint32_t)n * 128                                  \
                          + (((KS1) * 32 + (sub & 1) * 16) ^ (lrow << 4));     \
            uint32_t tmp[4];                                                   \
            ldsm_x4(tmp, (WB) + boff);                                         \
            b[2*p][0]   = tmp[0]; b[2*p][1]   = tmp[1];                        \
            b[2*p+1][0] = tmp[2]; b[2*p+1][1] = tmp[3];                        \
        }                                                                      \
        _Pragma("unroll")                                                      \
        for (int nt8 = 0; nt8 < 8; ++nt8) mma_f16(acc[nt8], a1, b[nt8]);       \
        slot = (slot == NSTAGE - 1) ? 0 : slot + 1;                            \
    }

    int rt_c = rt0;
    int slot = 0;
#pragma unroll 1
    for (int f2 = 0; f2 < npairs; ++f2) {
        const uint32_t wbase = smb + SM_W + (uint32_t)(f2 & 7) * 8192;

        HALF(wbase, 0, 1);   // even half-chunk: kk%4 = 0,1
        HALF(wbase, 2, 3);   // odd  half-chunk: kk%4 = 2,3

        // ---- tile boundary: store + reset ----
        if ((f2 & 7) == 7) {
            const int arow = rt_c * 16 + (lane >> 2);
#pragma unroll
            for (int nt8 = 0; nt8 < 8; ++nt8) {
                int gcol = nt8 * 8 + (lane & 3) * 2;
                __stcs((float2*)(out + (size_t)arow * NDIM + gcol),
                       make_float2(acc[nt8][0], acc[nt8][1]));
                __stcs((float2*)(out + (size_t)(arow + 8) * NDIM + gcol),
                       make_float2(acc[nt8][2], acc[nt8][3]));
#pragma unroll
                for (int q = 0; q < 4; ++q) acc[nt8][q] = 0.0f;
            }
            rt_c += rtstride;
        }
    }
}

extern "C" void kernel_launch(void* const* d_in, const int* in_sizes, int n_in,
                              void* d_out, int out_size) {
    const float* x = (const float*)d_in[0];   // [65536, 512]
    const float* W = (const float*)d_in[1];   // [512, 64]
    float* out = (float*)d_out;               // [65536, 64]

    cudaFuncSetAttribute(NN_57844619543085_kernel,
                         cudaFuncAttributeMaxDynamicSharedMemorySize, SMEM_TOTAL);

    int sms = 148;
    cudaDeviceGetAttribute(&sms, cudaDevAttrMultiProcessorCount, 0);

    NN_57844619543085_kernel<<<sms, THREADS, SMEM_TOTAL>>>(x, W, out);
}